// round 6
// baseline (speedup 1.0000x reference)
#include <cuda_runtime.h>
#include <math.h>

#define N_    4
#define D_    128
#define K_    1024
#define M_    32768            // rows per layer (B*H*W)
#define MT    128              // rows per CTA
#define KT    64               // codes per chunk
#define NCH   16               // K_/KT

#define Q_OFF    0
#define IDX_OFF  16777216
#define LOSS_OFF 16908288
#define PERP_OFF 16908292

// smem layout (floats): xdup[32768] | cb_s[8192] | x2_s[128] | red_s[16]
#define SMEM_FLOATS 41104
#define SMEM_BYTES  (SMEM_FLOATS * 4)

// device scratch (no allocations allowed)
__device__ float g_cbT[N_ * D_ * K_];     // codebook transposed [n][d][k]
__device__ float g_e2[N_ * K_];           // ||e_k||^2
__device__ float g_counts[N_ * K_];       // histogram (exact float +1 adds)
__device__ float g_losspart[N_ * 256];    // per-CTA loss partial sums
__device__ int   g_idx[N_ * M_];          // argmin indices

typedef unsigned long long ull;

__device__ __forceinline__ void ffma2(ull& a, ull x, ull y) {
    asm("fma.rn.f32x2 %0, %1, %2, %0;" : "+l"(a) : "l"(x), "l"(y));
}
__device__ __forceinline__ float2 u2f(ull v) {
    float2 r;
    asm("mov.b64 {%0, %1}, %2;" : "=f"(r.x), "=f"(r.y) : "l"(v));
    return r;
}

// ---------------------------------------------------------------------------
// ||e||^2 per code (one warp per code); zero histogram.  grid 512 x 256.
__global__ void vq_prep(const float* __restrict__ cb) {
    int w    = (blockIdx.x << 3) + (threadIdx.x >> 5);  // global code id 0..4095
    int lane = threadIdx.x & 31;
    const float4* cb4 = (const float4*)cb;
    float4 v = cb4[w * 32 + lane];
    float s = v.x * v.x + v.y * v.y + v.z * v.z + v.w * v.w;
    #pragma unroll
    for (int off = 16; off; off >>= 1) s += __shfl_xor_sync(0xffffffffu, s, off);
    if (lane == 0) g_e2[w] = s;
    if (lane == 1) g_counts[w] = 0.f;
}

// ---------------------------------------------------------------------------
// transpose [n][k][d] -> [n][d][k].  grid (32,4,4) x 256.
__global__ void vq_transpose(const float* __restrict__ cb) {
    __shared__ float t[32][33];
    int n = blockIdx.z, kt = blockIdx.x, dt = blockIdx.y;
    int tx = threadIdx.x & 31, ty = threadIdx.x >> 5;
    #pragma unroll
    for (int q = 0; q < 4; ++q) {
        int ky = ty + q * 8;
        t[ky][tx] = cb[(n * K_ + kt * 32 + ky) * D_ + dt * 32 + tx];
    }
    __syncthreads();
    #pragma unroll
    for (int q = 0; q < 4; ++q) {
        int dy = ty + q * 8;
        g_cbT[n * (D_ * K_) + (dt * 32 + dy) * K_ + kt * 32 + tx] = t[tx][dy];
    }
}

// ---------------------------------------------------------------------------
// main: one CTA = 128 rows x 1024 codes for one layer.  grid (256,4) x 256.
__global__ void __launch_bounds__(256)
vq_main(const float* __restrict__ x, float* __restrict__ out) {
    extern __shared__ float smem[];
    float* xdup  = smem;              // [d*256 + 2r] duplicated pairs
    float* cb_s  = smem + 32768;      // [d*64 + kk]
    float* x2_s  = smem + 40960;      // [128]
    float* red_s = smem + 41088;      // [16]

    const int tid = threadIdx.x;
    const int n   = blockIdx.y;
    const int m0  = blockIdx.x * MT;
    const int b   = m0 >> 10;
    const int hw0 = m0 & 1023;
    const int kg  = tid & 15;         // code group (4 codes)
    const int mg  = tid >> 4;         // row group (8 rows)

    // ---- load x tile (coalesced), store duplicated pairs to smem
    {
        const float4* xg = (const float4*)x;
        const int base4 = ((b * N_ + n) * D_) * 256 + (hw0 >> 2);
        const int rq = tid & 31;      // row quad: rows 4rq..4rq+3
        const int d0 = tid >> 5;
        #pragma unroll 4
        for (int p = 0; p < 16; ++p) {
            int d = d0 + p * 8;
            float4 v = xg[base4 + d * 256 + rq];
            float4* dst = (float4*)(xdup + d * 256 + rq * 8);
            dst[0] = make_float4(v.x, v.x, v.y, v.y);
            dst[1] = make_float4(v.z, v.z, v.w, v.w);
        }
    }
    __syncthreads();

    // ---- deterministic per-row ||x||^2
    if (tid < 128) {
        float s = 0.f;
        #pragma unroll 8
        for (int d = 0; d < 128; ++d) {
            float v = xdup[d * 256 + 2 * tid];
            s = fmaf(v, v, s);
        }
        x2_s[tid] = s;
    }
    __syncthreads();

    float x2r[8];
    #pragma unroll
    for (int r = 0; r < 8; ++r) x2r[r] = x2_s[mg * 8 + r];

    float best[8];
    int   bidx[8];
    #pragma unroll
    for (int r = 0; r < 8; ++r) { best[r] = 3.4e38f; bidx[r] = 0; }

    const float4* cbT4 = (const float4*)g_cbT;

    for (int c = 0; c < NCH; ++c) {
        const int kbase = c * KT + kg * 4;
        float e2v0 = g_e2[n * K_ + kbase + 0];
        float e2v1 = g_e2[n * K_ + kbase + 1];
        float e2v2 = g_e2[n * K_ + kbase + 2];
        float e2v3 = g_e2[n * K_ + kbase + 3];
        if (c) __syncthreads();
        {   // load codebook chunk [128 d][64 k]
            float4* cbs4 = (float4*)cb_s;
            const int cbase = n * 32768 + c * 16;
            #pragma unroll
            for (int i = 0; i < 8; ++i) {
                int j = tid + i * 256;
                int d = j >> 4, q = j & 15;
                cbs4[d * 16 + q] = cbT4[cbase + d * 256 + q];
            }
        }
        __syncthreads();

        ull acc[8][2];
        #pragma unroll
        for (int r = 0; r < 8; ++r) { acc[r][0] = 0ull; acc[r][1] = 0ull; }

        const float* xbase  = xdup + mg * 16;
        const float* cbbase = cb_s + kg * 4;
        #pragma unroll 4
        for (int d = 0; d < 128; ++d) {
            const float* xp = xbase + d * 256;
            ulonglong2 xa = *(const ulonglong2*)(xp);        // rows 0,1
            ulonglong2 xb = *(const ulonglong2*)(xp + 4);    // rows 2,3
            ulonglong2 xc = *(const ulonglong2*)(xp + 8);    // rows 4,5
            ulonglong2 xd = *(const ulonglong2*)(xp + 12);   // rows 6,7
            ulonglong2 cp = *(const ulonglong2*)(cbbase + d * 64);
            ffma2(acc[0][0], xa.x, cp.x); ffma2(acc[0][1], xa.x, cp.y);
            ffma2(acc[1][0], xa.y, cp.x); ffma2(acc[1][1], xa.y, cp.y);
            ffma2(acc[2][0], xb.x, cp.x); ffma2(acc[2][1], xb.x, cp.y);
            ffma2(acc[3][0], xb.y, cp.x); ffma2(acc[3][1], xb.y, cp.y);
            ffma2(acc[4][0], xc.x, cp.x); ffma2(acc[4][1], xc.x, cp.y);
            ffma2(acc[5][0], xc.y, cp.x); ffma2(acc[5][1], xc.y, cp.y);
            ffma2(acc[6][0], xd.x, cp.x); ffma2(acc[6][1], xd.x, cp.y);
            ffma2(acc[7][0], xd.y, cp.x); ffma2(acc[7][1], xd.y, cp.y);
        }

        // distances in reference op order: (x2 - 2*dot) + e2 ; strict < keeps low idx
        #pragma unroll
        for (int r = 0; r < 8; ++r) {
            float2 p01 = u2f(acc[r][0]);
            float2 p23 = u2f(acc[r][1]);
            float dd;
            dd = __fadd_rn(__fadd_rn(x2r[r], -2.f * p01.x), e2v0);
            if (dd < best[r]) { best[r] = dd; bidx[r] = kbase + 0; }
            dd = __fadd_rn(__fadd_rn(x2r[r], -2.f * p01.y), e2v1);
            if (dd < best[r]) { best[r] = dd; bidx[r] = kbase + 1; }
            dd = __fadd_rn(__fadd_rn(x2r[r], -2.f * p23.x), e2v2);
            if (dd < best[r]) { best[r] = dd; bidx[r] = kbase + 2; }
            dd = __fadd_rn(__fadd_rn(x2r[r], -2.f * p23.y), e2v3);
            if (dd < best[r]) { best[r] = dd; bidx[r] = kbase + 3; }
        }
    }

    // ---- argmin across the 16 kg lanes (low 4 lane bits)
    #pragma unroll
    for (int off = 1; off < 16; off <<= 1) {
        #pragma unroll
        for (int r = 0; r < 8; ++r) {
            float ob = __shfl_xor_sync(0xffffffffu, best[r], off);
            int   oi = __shfl_xor_sync(0xffffffffu, bidx[r], off);
            if (ob < best[r] || (ob == best[r] && oi < bidx[r])) {
                best[r] = ob; bidx[r] = oi;
            }
        }
    }

    if (kg == 0) {
        float ls = 0.f;
        #pragma unroll
        for (int r = 0; r < 8; ++r) {
            int row = mg * 8 + r;
            int hw  = hw0 + row;
            g_idx[n * M_ + m0 + row] = bidx[r];
            out[IDX_OFF + b * 4096 + n * 1024 + hw] = (float)bidx[r];
            atomicAdd(&g_counts[n * K_ + bidx[r]], 1.0f);
            ls += best[r];
        }
        red_s[mg] = ls;
    }
    __syncthreads();
    if (tid == 0) {
        float tot = 0.f;
        #pragma unroll
        for (int i = 0; i < 16; ++i) tot += red_s[i];
        g_losspart[n * 256 + blockIdx.x] = tot;
    }
}

// ---------------------------------------------------------------------------
// gather quantized vectors -> [B, N*D, H, W].  grid (16,4,32) x 256.
__global__ void vq_gather(const float* __restrict__ cb, float* __restrict__ out) {
    __shared__ float s[64 * 129];
    int b = blockIdx.z, n = blockIdx.y;
    int hw0 = blockIdx.x * 64;
    int w = threadIdx.x >> 5, lane = threadIdx.x & 31;
    const float4* cb4 = (const float4*)cb;
    #pragma unroll
    for (int j = 0; j < 8; ++j) {
        int row = w + j * 8;
        int idx = g_idx[n * M_ + b * 1024 + hw0 + row];
        float4 v = cb4[(n * K_ + idx) * 32 + lane];
        float* dst = s + row * 129 + lane * 4;
        dst[0] = v.x; dst[1] = v.y; dst[2] = v.z; dst[3] = v.w;
    }
    __syncthreads();
    float4* o4 = (float4*)out;
    int obase = ((b * (N_ * D_) + n * D_) * 1024 + hw0) >> 2;
    #pragma unroll
    for (int i = 0; i < 8; ++i) {
        int lin = threadIdx.x + i * 256;
        int d = lin >> 4, q = lin & 15;
        float4 v = make_float4(s[(q * 4 + 0) * 129 + d],
                               s[(q * 4 + 1) * 129 + d],
                               s[(q * 4 + 2) * 129 + d],
                               s[(q * 4 + 3) * 129 + d]);
        o4[obase + d * 256 + q] = v;
    }
}

// ---------------------------------------------------------------------------
// loss + perplexity per layer.  grid 4 x 256.
__global__ void vq_final(float* __restrict__ out) {
    __shared__ float sb[256];
    int n = blockIdx.x, t = threadIdx.x;
    sb[t] = g_losspart[n * 256 + t];
    __syncthreads();
    if (t == 0) {
        float tot = 0.f;
        for (int i = 0; i < 256; ++i) tot += sb[i];
        out[LOSS_OFF + n] = 1.25f * (tot / (32768.f * 128.f));
    }
    __syncthreads();
    float h = 0.f;
    #pragma unroll
    for (int j = 0; j < 4; ++j) {
        float cnt = g_counts[n * K_ + t * 4 + j];
        float p = cnt / 32768.f;
        h += p * logf(p + 1e-10f);
    }
    sb[t] = h;
    __syncthreads();
    if (t == 0) {
        float tot = 0.f;
        for (int i = 0; i < 256; ++i) tot += sb[i];
        out[PERP_OFF + n] = expf(-tot);
    }
}

// ---------------------------------------------------------------------------
extern "C" void kernel_launch(void* const* d_in, const int* in_sizes, int n_in,
                              void* d_out, int out_size) {
    const float* x  = (const float*)d_in[0];   // [32, 512, 32, 32]
    const float* cb = (const float*)d_in[1];   // [4, 1024, 128]
    float* out = (float*)d_out;
    (void)in_sizes; (void)n_in; (void)out_size;

    cudaFuncSetAttribute(vq_main, cudaFuncAttributeMaxDynamicSharedMemorySize,
                         SMEM_BYTES);

    vq_prep<<<512, 256>>>(cb);
    vq_transpose<<<dim3(32, 4, 4), 256>>>(cb);
    vq_main<<<dim3(256, 4), 256, SMEM_BYTES>>>(x, out);
    vq_gather<<<dim3(16, 4, 32), 256>>>(cb, out);
    vq_final<<<4, 256>>>(out);
}